// round 6
// baseline (speedup 1.0000x reference)
#include <cuda_runtime.h>

#define BATCH      1024
#define INPUT_DIM  1024
#define NB_K       32
#define KDIM       16
#define OUT_COLS   (INPUT_DIM + NB_K)   // 1056
#define DSPLIT     8
#define DCHUNK     (INPUT_DIM / DSPLIT) // 128

// Partial activations per d-split, then reduced into g_act.
__device__ float g_part[(size_t)DSPLIT * NB_K * BATCH * KDIM];  // 16 MB
__device__ float g_act [(size_t)NB_K * BATCH * KDIM];           // 2 MB

// ---- packed f32x2 helpers ------------------------------------------------
#define FMA_F32X2(d, a, b, c) \
    asm("fma.rn.f32x2 %0, %1, %2, %3;" : "=l"(d) : "l"(a), "l"(b), "l"(c))
#define ADD_F32X2(d, a, b) \
    asm("add.rn.f32x2 %0, %1, %2;" : "=l"(d) : "l"(a), "l"(b))
#define ABS2_F32X2(d, a) \
    asm("and.b64 %0, %1, 0x7FFFFFFF7FFFFFFF;" : "=l"(d) : "l"(a))
#define PACK_F32X2(d, lo, hi) \
    asm("mov.b64 %0, {%1, %2};" : "=l"(d) : "f"(lo), "f"(hi))
#define UNPACK_F32X2(lo, hi, v) \
    asm("mov.b64 {%0, %1}, %2;" : "=f"(lo), "=f"(hi) : "l"(v))

// ---------------------------------------------------------------------------
// Kernel A: partial GEMM over one d-chunk of 128.
// grid = (32 k, 4 b-tiles of 256, 8 d-splits) = 1024 blocks, block = 256.
// Thread t: bl = t&127 -> b rows {b0+bl, b0+bl+128}; h = t>>7 -> m in [8h,8h+8).
// ---------------------------------------------------------------------------
__global__ void __launch_bounds__(256) mbd_gemm_kernel(
    const float* __restrict__ x, const float* __restrict__ W)
{
    const int k     = blockIdx.x;
    const int b0    = blockIdx.y * 256;
    const int dbase = blockIdx.z * DCHUNK;
    const int tid   = threadIdx.x;
    const int bl    = tid & 127;
    const int h     = tid >> 7;

    __shared__ float sx[256][33];    // 256 b-rows x 32 d, padded
    __shared__ float sw[32][16];

    unsigned long long accA0 = 0ull, accA1 = 0ull, accA2 = 0ull, accA3 = 0ull;
    unsigned long long accB0 = 0ull, accB1 = 0ull, accB2 = 0ull, accB3 = 0ull;

    const float4* x4 = reinterpret_cast<const float4*>(x);

    for (int d0 = dbase; d0 < dbase + DCHUNK; d0 += 32) {
        // x tile: 256 rows x 32 d = 2048 float4, 8 per thread
#pragma unroll
        for (int i = 0; i < 8; i++) {
            int idx = tid + i * 256;
            int r = idx >> 3;
            int c = idx & 7;
            float4 v = x4[(size_t)(b0 + r) * (INPUT_DIM / 4) + (d0 >> 2) + c];
            sx[r][c * 4 + 0] = v.x;
            sx[r][c * 4 + 1] = v.y;
            sx[r][c * 4 + 2] = v.z;
            sx[r][c * 4 + 3] = v.w;
        }
        // W tile: 32 d x 16 m = 512 contiguous floats = 128 float4
        if (tid < 128) {
            const float4* w4 = reinterpret_cast<const float4*>(
                W + (size_t)k * INPUT_DIM * KDIM + (size_t)d0 * KDIM);
            reinterpret_cast<float4*>(&sw[0][0])[tid] = w4[tid];
        }
        __syncthreads();

#pragma unroll
        for (int dd = 0; dd < 32; dd++) {
            float xa = sx[bl][dd];
            float xb = sx[bl + 128][dd];
            unsigned long long xxa, xxb;
            PACK_F32X2(xxa, xa, xa);
            PACK_F32X2(xxb, xb, xb);
            const ulonglong2* wp = reinterpret_cast<const ulonglong2*>(&sw[dd][h * 8]);
            ulonglong2 wlo = wp[0];
            ulonglong2 whi = wp[1];
            FMA_F32X2(accA0, wlo.x, xxa, accA0);
            FMA_F32X2(accA1, wlo.y, xxa, accA1);
            FMA_F32X2(accA2, whi.x, xxa, accA2);
            FMA_F32X2(accA3, whi.y, xxa, accA3);
            FMA_F32X2(accB0, wlo.x, xxb, accB0);
            FMA_F32X2(accB1, wlo.y, xxb, accB1);
            FMA_F32X2(accB2, whi.x, xxb, accB2);
            FMA_F32X2(accB3, whi.y, xxb, accB3);
        }
        __syncthreads();
    }

    float* base = g_part + ((size_t)blockIdx.z * NB_K + k) * BATCH * KDIM;
    {
        float r0, r1, r2, r3, r4, r5, r6, r7;
        UNPACK_F32X2(r0, r1, accA0); UNPACK_F32X2(r2, r3, accA1);
        UNPACK_F32X2(r4, r5, accA2); UNPACK_F32X2(r6, r7, accA3);
        float4* o4 = reinterpret_cast<float4*>(
            base + (size_t)(b0 + bl) * KDIM + h * 8);
        o4[0] = make_float4(r0, r1, r2, r3);
        o4[1] = make_float4(r4, r5, r6, r7);
    }
    {
        float r0, r1, r2, r3, r4, r5, r6, r7;
        UNPACK_F32X2(r0, r1, accB0); UNPACK_F32X2(r2, r3, accB1);
        UNPACK_F32X2(r4, r5, accB2); UNPACK_F32X2(r6, r7, accB3);
        float4* o4 = reinterpret_cast<float4*>(
            base + (size_t)(b0 + bl + 128) * KDIM + h * 8);
        o4[0] = make_float4(r0, r1, r2, r3);
        o4[1] = make_float4(r4, r5, r6, r7);
    }
}

// ---------------------------------------------------------------------------
// Kernel A2: g_act = sum over the 8 d-split partials (float4 granularity).
// ---------------------------------------------------------------------------
__global__ void __launch_bounds__(256) mbd_reduce_kernel()
{
    const size_t n4 = (size_t)NB_K * BATCH * KDIM / 4;   // 131072
    size_t i = (size_t)blockIdx.x * 256 + threadIdx.x;
    if (i >= n4) return;
    const float4* p = reinterpret_cast<const float4*>(g_part);
    float4 s = p[i];
#pragma unroll
    for (int z = 1; z < DSPLIT; z++) {
        float4 t = p[i + (size_t)z * n4];
        s.x += t.x; s.y += t.y; s.z += t.z; s.w += t.w;
    }
    reinterpret_cast<float4*>(g_act)[i] = s;
}

// ---------------------------------------------------------------------------
// Kernel B: feat[b][k] = sum_c exp(-sum_m |act[k][b][m] - act[k][c][m]|)
// grid (32 k, 4 b-tiles), block 256, one b per thread, 32KB smem chunks of
// 512 NEGATED rows. diff = add.f32x2(a, -v); abs via and.b64 (ALU pipe);
// packed f32x2 reduction tree; __expf on MUFU.
// Also folds the x -> out[:, :1024] copy (memory-bound, hidden under compute).
// Row layout in smem: row r = ulonglong2 indices [4r, 4r+4)  (16 floats = 64B).
// ---------------------------------------------------------------------------
__global__ void __launch_bounds__(256) mbd_pairwise_kernel(
    const float* __restrict__ x, float* __restrict__ out)
{
    const int k   = blockIdx.x;
    const int tid = threadIdx.x;
    const int b   = blockIdx.y * 256 + tid;

    __shared__ ulonglong2 sneg[512 * 4];   // 512 rows x 64B = 32 KB

    // ---- folded copy: each of the 128 blocks copies 8 rows of x ----
    {
        const int id = blockIdx.x * 4 + blockIdx.y;       // 0..127
        const float4* x4 = reinterpret_cast<const float4*>(x);
        float4*       o4 = reinterpret_cast<float4*>(out);
#pragma unroll
        for (int i = 0; i < 8; i++) {
            int row = id * 8 + i;
            o4[(size_t)row * (OUT_COLS / 4) + tid] =
                x4[(size_t)row * (INPUT_DIM / 4) + tid];
        }
    }

    const float4* actk = reinterpret_cast<const float4*>(
        g_act + (size_t)k * BATCH * KDIM);

    // my own activation row, packed as 8 f32x2
    unsigned long long a[8];
    {
        float4 a0 = actk[b * 4 + 0];
        float4 a1 = actk[b * 4 + 1];
        float4 a2 = actk[b * 4 + 2];
        float4 a3 = actk[b * 4 + 3];
        PACK_F32X2(a[0], a0.x, a0.y);  PACK_F32X2(a[1], a0.z, a0.w);
        PACK_F32X2(a[2], a1.x, a1.y);  PACK_F32X2(a[3], a1.z, a1.w);
        PACK_F32X2(a[4], a2.x, a2.y);  PACK_F32X2(a[5], a2.z, a2.w);
        PACK_F32X2(a[6], a3.x, a3.y);  PACK_F32X2(a[7], a3.z, a3.w);
    }

    float f = 0.f;

    for (int c0 = 0; c0 < BATCH; c0 += 512) {
        __syncthreads();   // previous chunk fully consumed before overwrite
        // stage 512 negated rows: 2048 float4 / 256 threads = 8 each
#pragma unroll
        for (int i = 0; i < 8; i++) {
            float4 v = actk[c0 * 4 + tid + i * 256];
            v.x = -v.x; v.y = -v.y; v.z = -v.z; v.w = -v.w;
            reinterpret_cast<float4*>(sneg)[tid + i * 256] = v;
        }
        __syncthreads();

#pragma unroll 4
        for (int c = 0; c < 512; c++) {
            ulonglong2 w0 = sneg[c * 4 + 0];
            ulonglong2 w1 = sneg[c * 4 + 1];
            ulonglong2 w2 = sneg[c * 4 + 2];
            ulonglong2 w3 = sneg[c * 4 + 3];

            unsigned long long d0, d1, d2, d3, d4, d5, d6, d7;
            ADD_F32X2(d0, a[0], w0.x);  ADD_F32X2(d1, a[1], w0.y);
            ADD_F32X2(d2, a[2], w1.x);  ADD_F32X2(d3, a[3], w1.y);
            ADD_F32X2(d4, a[4], w2.x);  ADD_F32X2(d5, a[5], w2.y);
            ADD_F32X2(d6, a[6], w3.x);  ADD_F32X2(d7, a[7], w3.y);

            ABS2_F32X2(d0, d0);  ABS2_F32X2(d1, d1);
            ABS2_F32X2(d2, d2);  ABS2_F32X2(d3, d3);
            ABS2_F32X2(d4, d4);  ABS2_F32X2(d5, d5);
            ABS2_F32X2(d6, d6);  ABS2_F32X2(d7, d7);

            ADD_F32X2(d0, d0, d1);
            ADD_F32X2(d2, d2, d3);
            ADD_F32X2(d4, d4, d5);
            ADD_F32X2(d6, d6, d7);
            ADD_F32X2(d0, d0, d2);
            ADD_F32X2(d4, d4, d6);
            ADD_F32X2(d0, d0, d4);

            float slo, shi;
            UNPACK_F32X2(slo, shi, d0);
            f += __expf(-(slo + shi));
        }
    }

    out[(size_t)b * OUT_COLS + INPUT_DIM + k] = f;
}

extern "C" void kernel_launch(void* const* d_in, const int* in_sizes, int n_in,
                              void* d_out, int out_size)
{
    (void)in_sizes; (void)n_in; (void)out_size;
    const float* x = (const float*)d_in[0];
    const float* W = (const float*)d_in[1];
    float* out = (float*)d_out;

    mbd_gemm_kernel<<<dim3(NB_K, BATCH / 256, DSPLIT), 256>>>(x, W);
    mbd_reduce_kernel<<<(NB_K * BATCH * KDIM / 4 + 255) / 256, 256>>>();
    mbd_pairwise_kernel<<<dim3(NB_K, BATCH / 256), 256>>>(x, out);
}

// round 7
// speedup vs baseline: 1.2591x; 1.2591x over previous
#include <cuda_runtime.h>

#define BATCH      1024
#define INPUT_DIM  1024
#define NB_K       32
#define KDIM       16
#define OUT_COLS   (INPUT_DIM + NB_K)   // 1056
#define DSPLIT     8
#define DCHUNK     (INPUT_DIM / DSPLIT) // 128

// Partial activations per d-split, then reduced into g_act.
__device__ float g_part[(size_t)DSPLIT * NB_K * BATCH * KDIM];  // 16 MB
__device__ float g_act [(size_t)NB_K * BATCH * KDIM];           // 2 MB

// ---- packed f32x2 helpers (GEMM only — proven win there) ------------------
#define FMA_F32X2(d, a, b, c) \
    asm("fma.rn.f32x2 %0, %1, %2, %3;" : "=l"(d) : "l"(a), "l"(b), "l"(c))
#define PACK_F32X2(d, lo, hi) \
    asm("mov.b64 %0, {%1, %2};" : "=l"(d) : "f"(lo), "f"(hi))
#define UNPACK_F32X2(lo, hi, v) \
    asm("mov.b64 {%0, %1}, %2;" : "=f"(lo), "=f"(hi) : "l"(v))

// ---------------------------------------------------------------------------
// Kernel A: partial GEMM over one d-chunk of 128.  (verified: 41.4us)
// grid = (32 k, 4 b-tiles of 256, 8 d-splits) = 1024 blocks, block = 256.
// ---------------------------------------------------------------------------
__global__ void __launch_bounds__(256) mbd_gemm_kernel(
    const float* __restrict__ x, const float* __restrict__ W)
{
    const int k     = blockIdx.x;
    const int b0    = blockIdx.y * 256;
    const int dbase = blockIdx.z * DCHUNK;
    const int tid   = threadIdx.x;
    const int bl    = tid & 127;
    const int h     = tid >> 7;

    __shared__ float sx[256][33];
    __shared__ float sw[32][16];

    unsigned long long accA0 = 0ull, accA1 = 0ull, accA2 = 0ull, accA3 = 0ull;
    unsigned long long accB0 = 0ull, accB1 = 0ull, accB2 = 0ull, accB3 = 0ull;

    const float4* x4 = reinterpret_cast<const float4*>(x);

    for (int d0 = dbase; d0 < dbase + DCHUNK; d0 += 32) {
#pragma unroll
        for (int i = 0; i < 8; i++) {
            int idx = tid + i * 256;
            int r = idx >> 3;
            int c = idx & 7;
            float4 v = x4[(size_t)(b0 + r) * (INPUT_DIM / 4) + (d0 >> 2) + c];
            sx[r][c * 4 + 0] = v.x;
            sx[r][c * 4 + 1] = v.y;
            sx[r][c * 4 + 2] = v.z;
            sx[r][c * 4 + 3] = v.w;
        }
        if (tid < 128) {
            const float4* w4 = reinterpret_cast<const float4*>(
                W + (size_t)k * INPUT_DIM * KDIM + (size_t)d0 * KDIM);
            reinterpret_cast<float4*>(&sw[0][0])[tid] = w4[tid];
        }
        __syncthreads();

#pragma unroll
        for (int dd = 0; dd < 32; dd++) {
            float xa = sx[bl][dd];
            float xb = sx[bl + 128][dd];
            unsigned long long xxa, xxb;
            PACK_F32X2(xxa, xa, xa);
            PACK_F32X2(xxb, xb, xb);
            const ulonglong2* wp = reinterpret_cast<const ulonglong2*>(&sw[dd][h * 8]);
            ulonglong2 wlo = wp[0];
            ulonglong2 whi = wp[1];
            FMA_F32X2(accA0, wlo.x, xxa, accA0);
            FMA_F32X2(accA1, wlo.y, xxa, accA1);
            FMA_F32X2(accA2, whi.x, xxa, accA2);
            FMA_F32X2(accA3, whi.y, xxa, accA3);
            FMA_F32X2(accB0, wlo.x, xxb, accB0);
            FMA_F32X2(accB1, wlo.y, xxb, accB1);
            FMA_F32X2(accB2, whi.x, xxb, accB2);
            FMA_F32X2(accB3, whi.y, xxb, accB3);
        }
        __syncthreads();
    }

    float* base = g_part + ((size_t)blockIdx.z * NB_K + k) * BATCH * KDIM;
    {
        float r0, r1, r2, r3, r4, r5, r6, r7;
        UNPACK_F32X2(r0, r1, accA0); UNPACK_F32X2(r2, r3, accA1);
        UNPACK_F32X2(r4, r5, accA2); UNPACK_F32X2(r6, r7, accA3);
        float4* o4 = reinterpret_cast<float4*>(
            base + (size_t)(b0 + bl) * KDIM + h * 8);
        o4[0] = make_float4(r0, r1, r2, r3);
        o4[1] = make_float4(r4, r5, r6, r7);
    }
    {
        float r0, r1, r2, r3, r4, r5, r6, r7;
        UNPACK_F32X2(r0, r1, accB0); UNPACK_F32X2(r2, r3, accB1);
        UNPACK_F32X2(r4, r5, accB2); UNPACK_F32X2(r6, r7, accB3);
        float4* o4 = reinterpret_cast<float4*>(
            base + (size_t)(b0 + bl + 128) * KDIM + h * 8);
        o4[0] = make_float4(r0, r1, r2, r3);
        o4[1] = make_float4(r4, r5, r6, r7);
    }
}

// ---------------------------------------------------------------------------
// Kernel A2: g_act = sum over the 8 d-split partials.
// ---------------------------------------------------------------------------
__global__ void __launch_bounds__(256) mbd_reduce_kernel()
{
    const size_t n4 = (size_t)NB_K * BATCH * KDIM / 4;   // 131072
    size_t i = (size_t)blockIdx.x * 256 + threadIdx.x;
    if (i >= n4) return;
    const float4* p = reinterpret_cast<const float4*>(g_part);
    float4 s = p[i];
#pragma unroll
    for (int z = 1; z < DSPLIT; z++) {
        float4 t = p[i + (size_t)z * n4];
        s.x += t.x; s.y += t.y; s.z += t.z; s.w += t.w;
    }
    reinterpret_cast<float4*>(g_act)[i] = s;
}

// ---------------------------------------------------------------------------
// Kernel B: feat[b][k] = sum_c exp(-sum_m |act[k][b][m] - act[k][c][m]|)
// EXACT R1 scalar version (verified ~31.6us; abs folds into FADD src
// modifiers, which is why it beats packed variants) + folded x-copy.
// grid = (32 k, 4 b-tiles), block = 256 (one b per thread).
// ---------------------------------------------------------------------------
__global__ void __launch_bounds__(256) mbd_pairwise_kernel(
    const float* __restrict__ x, float* __restrict__ out)
{
    const int k   = blockIdx.x;
    const int tid = threadIdx.x;
    const int b   = blockIdx.y * 256 + tid;

    __shared__ float4 sa[512 * 4];   // 512 rows x 16 floats = 32 KB

    // ---- folded copy: each of the 128 blocks copies 8 rows of x ----
    {
        const int id = blockIdx.x * 4 + blockIdx.y;       // 0..127
        const float4* x4 = reinterpret_cast<const float4*>(x);
        float4*       o4 = reinterpret_cast<float4*>(out);
#pragma unroll
        for (int i = 0; i < 8; i++) {
            int row = id * 8 + i;
            o4[(size_t)row * (OUT_COLS / 4) + tid] =
                x4[(size_t)row * (INPUT_DIM / 4) + tid];
        }
    }

    const float4* actk = reinterpret_cast<const float4*>(
        g_act + (size_t)k * BATCH * KDIM);

    float4 a0 = actk[b * 4 + 0];
    float4 a1 = actk[b * 4 + 1];
    float4 a2 = actk[b * 4 + 2];
    float4 a3 = actk[b * 4 + 3];

    float f = 0.f;

    for (int c0 = 0; c0 < BATCH; c0 += 512) {
        __syncthreads();
#pragma unroll
        for (int i = 0; i < 8; i++)
            sa[tid + i * 256] = actk[c0 * 4 + tid + i * 256];
        __syncthreads();

#pragma unroll 4
        for (int c = 0; c < 512; c++) {
            float4 v0 = sa[c * 4 + 0];
            float4 v1 = sa[c * 4 + 1];
            float4 v2 = sa[c * 4 + 2];
            float4 v3 = sa[c * 4 + 3];
            float s0 = fabsf(a0.x - v0.x) + fabsf(a0.y - v0.y)
                     + fabsf(a0.z - v0.z) + fabsf(a0.w - v0.w);
            float s1 = fabsf(a1.x - v1.x) + fabsf(a1.y - v1.y)
                     + fabsf(a1.z - v1.z) + fabsf(a1.w - v1.w);
            float s2 = fabsf(a2.x - v2.x) + fabsf(a2.y - v2.y)
                     + fabsf(a2.z - v2.z) + fabsf(a2.w - v2.w);
            float s3 = fabsf(a3.x - v3.x) + fabsf(a3.y - v3.y)
                     + fabsf(a3.z - v3.z) + fabsf(a3.w - v3.w);
            float s = (s0 + s1) + (s2 + s3);
            f += __expf(-s);
        }
    }

    out[(size_t)b * OUT_COLS + INPUT_DIM + k] = f;
}

extern "C" void kernel_launch(void* const* d_in, const int* in_sizes, int n_in,
                              void* d_out, int out_size)
{
    (void)in_sizes; (void)n_in; (void)out_size;
    const float* x = (const float*)d_in[0];
    const float* W = (const float*)d_in[1];
    float* out = (float*)d_out;

    mbd_gemm_kernel<<<dim3(NB_K, BATCH / 256, DSPLIT), 256>>>(x, W);
    mbd_reduce_kernel<<<(NB_K * BATCH * KDIM / 4 + 255) / 256, 256>>>();
    mbd_pairwise_kernel<<<dim3(NB_K, BATCH / 256), 256>>>(x, out);
}